// round 13
// baseline (speedup 1.0000x reference)
#include <cuda_runtime.h>
#include <cuda_bf16.h>
#include <mma.h>
#include <cstdint>

using namespace nvcuda;

#define B_   2
#define L_   2048
#define D_   1024
#define H_   16
#define DH_  64
#define M_   (B_*L_)          // 4096 rows
#define K2_  2048             // split-K (hi/lo interleaved)
#define SCALE 0.125f          // 1/sqrt(64)

// ---------------- scratch (static device memory; no allocs) ----------------
__device__ float g_v[M_*D_];
__device__ __nv_bfloat16 g_xs [M_*K2_];
__device__ __nv_bfloat16 g_cs [M_*K2_];
__device__ __nv_bfloat16 g_wqs[D_*K2_];   // weights, (hi,lo) interleaved
__device__ __nv_bfloat16 g_wks[D_*K2_];
__device__ __nv_bfloat16 g_wvs[D_*K2_];
__device__ __nv_bfloat16 g_wos[D_*K2_];
__device__ __nv_bfloat16 g_wqw[D_*K2_];   // weights, (lo,hi) swapped
__device__ __nv_bfloat16 g_wkw[D_*K2_];
__device__ __nv_bfloat16 g_wvw[D_*K2_];
__device__ __nv_bfloat16 g_wow[D_*K2_];
// attention split operands
__device__ __nv_bfloat16 g_qs [(size_t)B_*H_*L_*128];   // Q*scale (hi,lo)
__device__ __nv_bfloat16 g_qsw[(size_t)B_*H_*L_*128];   // Q*scale (lo,hi)
__device__ __nv_bfloat16 g_ks [(size_t)B_*H_*L_*128];   // K (hi,lo)
__device__ __nv_bfloat16 g_vs [(size_t)B_*H_*DH_*2*L_]; // V^T (hi,lo along key)

// ---------------- hi/lo bf16 pair packing ----------------
__device__ __forceinline__ uint32_t pack_hl(float x) {
    __nv_bfloat16 h = __float2bfloat16(x);
    __nv_bfloat16 l = __float2bfloat16(x - __bfloat162float(h));
    return (uint32_t)__bfloat16_as_ushort(h) |
           ((uint32_t)__bfloat16_as_ushort(l) << 16);
}
__device__ __forceinline__ uint32_t pack_lh(float x) {
    __nv_bfloat16 h = __float2bfloat16(x);
    __nv_bfloat16 l = __float2bfloat16(x - __bfloat162float(h));
    return (uint32_t)__bfloat16_as_ushort(l) |
           ((uint32_t)__bfloat16_as_ushort(h) << 16);
}

// ---------------- split kernels (inputs) ----------------
__global__ __launch_bounds__(256)
void split_x(const float* __restrict__ src, int n4)
{
    int i = blockIdx.x * 256 + threadIdx.x;
    if (i >= n4) return;
    float4 v = ((const float4*)src)[i];
    uint4 o;
    o.x = pack_hl(v.x); o.y = pack_hl(v.y); o.z = pack_hl(v.z); o.w = pack_hl(v.w);
    ((uint4*)g_xs)[i] = o;
}

__global__ __launch_bounds__(256)
void split_w(const float* __restrict__ src, int tag, int n4)
{
    __nv_bfloat16* dn = tag == 0 ? g_wqs : tag == 1 ? g_wks : tag == 2 ? g_wvs : g_wos;
    __nv_bfloat16* ds = tag == 0 ? g_wqw : tag == 1 ? g_wkw : tag == 2 ? g_wvw : g_wow;
    int i = blockIdx.x * 256 + threadIdx.x;
    if (i >= n4) return;
    float4 v = ((const float4*)src)[i];
    uint4 on, os;
    on.x = pack_hl(v.x); os.x = pack_lh(v.x);
    on.y = pack_hl(v.y); os.y = pack_lh(v.y);
    on.z = pack_hl(v.z); os.z = pack_lh(v.z);
    on.w = pack_hl(v.w); os.w = pack_lh(v.w);
    ((uint4*)dn)[i] = on;
    ((uint4*)ds)[i] = os;
}

// V transpose + split along key: g_v [bh][l][d] -> g_vs [bh][d][2l]
__global__ __launch_bounds__(256)
void v_split()
{
    __shared__ float tile[128 * 65];
    const int lb = blockIdx.x;
    const int bh = blockIdx.y;
    const int tid = threadIdx.x;
    const float* src = g_v + ((size_t)bh * L_ + lb * 128) * DH_;
    for (int i = 0; i < 8; i++) {
        int u = tid + i * 256;
        int r = u >> 4, q = u & 15;
        float4 t = ((const float4*)(src + (size_t)r * DH_))[q];
        tile[r * 65 + q * 4 + 0] = t.x;
        tile[r * 65 + q * 4 + 1] = t.y;
        tile[r * 65 + q * 4 + 2] = t.z;
        tile[r * 65 + q * 4 + 3] = t.w;
    }
    __syncthreads();
    const int d = tid >> 2, part = tid & 3;
    uint32_t* dst = (uint32_t*)g_vs + ((size_t)bh * DH_ + d) * L_
                    + lb * 128 + part * 32;
    #pragma unroll
    for (int j = 0; j < 32; j++) {
        float val = tile[(part * 32 + j) * 65 + d];
        dst[j] = pack_hl(val);
    }
}

// ---------------- WMMA GEMM (projections) — fused passes, fused split epi --
// which: 0 = qkv (mat selects Q/K/V; Q->g_qs/g_qsw scaled, K->g_ks, V->g_v)
//        1 = out projection (writes out_dst row-major)
#define TM 128
#define TN 128
#define BK 32
#define NCH (K2_ / BK)        // 64
#define AS 40
#define STG 20

__global__ __launch_bounds__(256)
void mma_gemm(int which,
              const float* __restrict__ bi0, const float* __restrict__ bi1,
              const float* __restrict__ bi2, float* __restrict__ out_dst)
{
    __shared__ __align__(16) __nv_bfloat16 sA [TM * AS];
    __shared__ __align__(16) __nv_bfloat16 sBn[TN * AS];
    __shared__ __align__(16) __nv_bfloat16 sBw[TN * AS];
    __shared__ __align__(16) float stage[8][16 * STG];

    const int mat = blockIdx.z;
    const __nv_bfloat16* A = (which == 0) ? g_xs : g_cs;
    const __nv_bfloat16* Bn =
        (which == 1) ? g_wos : (mat == 0 ? g_wqs : (mat == 1 ? g_wks : g_wvs));
    const __nv_bfloat16* Bw =
        (which == 1) ? g_wow : (mat == 0 ? g_wqw : (mat == 1 ? g_wkw : g_wvw));
    const float* bias = (mat == 0) ? bi0 : (mat == 1 ? bi1 : bi2);

    const int row0 = blockIdx.x * TM;
    const int col0 = blockIdx.y * TN;
    const int tid  = threadIdx.x;
    const int wid  = tid >> 5, lane = tid & 31;
    const int wr   = wid >> 2;
    const int wc   = wid & 3;

    wmma::fragment<wmma::accumulator, 16, 16, 16, float> acc[4][2];
    #pragma unroll
    for (int i = 0; i < 4; i++)
        #pragma unroll
        for (int j = 0; j < 2; j++)
            wmma::fill_fragment(acc[i][j], 0.0f);

    const int r0c = tid >> 2,          q0c = tid & 3;
    const int r1c = (tid + 256) >> 2,  q1c = (tid + 256) & 3;

    for (int ch = 0; ch < NCH; ch++) {
        const int k0g = ch * BK;
        __syncthreads();
        *(uint4*)&sA [r0c * AS + q0c * 8] =
            *(const uint4*)(A  + (size_t)(row0 + r0c) * K2_ + k0g + q0c * 8);
        *(uint4*)&sA [r1c * AS + q1c * 8] =
            *(const uint4*)(A  + (size_t)(row0 + r1c) * K2_ + k0g + q1c * 8);
        *(uint4*)&sBn[r0c * AS + q0c * 8] =
            *(const uint4*)(Bn + (size_t)(col0 + r0c) * K2_ + k0g + q0c * 8);
        *(uint4*)&sBn[r1c * AS + q1c * 8] =
            *(const uint4*)(Bn + (size_t)(col0 + r1c) * K2_ + k0g + q1c * 8);
        *(uint4*)&sBw[r0c * AS + q0c * 8] =
            *(const uint4*)(Bw + (size_t)(col0 + r0c) * K2_ + k0g + q0c * 8);
        *(uint4*)&sBw[r1c * AS + q1c * 8] =
            *(const uint4*)(Bw + (size_t)(col0 + r1c) * K2_ + k0g + q1c * 8);
        __syncthreads();

        #pragma unroll
        for (int kk = 0; kk < 2; kk++) {
            const int k0 = kk * 16;
            wmma::fragment<wmma::matrix_a, 16, 16, 16, __nv_bfloat16,
                           wmma::row_major> af[4];
            #pragma unroll
            for (int i = 0; i < 4; i++)
                wmma::load_matrix_sync(af[i], &sA[(wr * 64 + i * 16) * AS + k0], AS);
            wmma::fragment<wmma::matrix_b, 16, 16, 16, __nv_bfloat16,
                           wmma::col_major> bfn[2], bfw[2];
            #pragma unroll
            for (int j = 0; j < 2; j++) {
                wmma::load_matrix_sync(bfn[j], &sBn[(wc * 32 + j * 16) * AS + k0], AS);
                wmma::load_matrix_sync(bfw[j], &sBw[(wc * 32 + j * 16) * AS + k0], AS);
            }
            #pragma unroll
            for (int i = 0; i < 4; i++)
                #pragma unroll
                for (int j = 0; j < 2; j++) {
                    wmma::mma_sync(acc[i][j], af[i], bfn[j], acc[i][j]);
                    wmma::mma_sync(acc[i][j], af[i], bfw[j], acc[i][j]);
                }
        }
    }

    // ---- epilogue: bias add + destination-specific packing ----
    __syncthreads();
    #pragma unroll
    for (int i = 0; i < 4; i++) {
        #pragma unroll
        for (int j = 0; j < 2; j++) {
            wmma::store_matrix_sync(&stage[wid][0], acc[i][j], STG,
                                    wmma::mem_row_major);
            __syncwarp();
            #pragma unroll
            for (int e = 0; e < 8; e++) {
                int idx = lane * 8 + e;
                int rr = idx >> 4, cc = idx & 15;
                int m = row0 + wr * 64 + i * 16 + rr;
                int n = col0 + wc * 32 + j * 16 + cc;
                float v = stage[wid][rr * STG + cc] + bias[n];
                if (which == 1) {
                    out_dst[(size_t)m * D_ + n] = v;
                } else {
                    int l = m & (L_ - 1), bb = m >> 11;
                    int h = n >> 6, d = n & 63;
                    size_t hrow = ((size_t)(bb * H_ + h) * L_ + l);
                    if (mat == 0) {
                        float w = v * SCALE;
                        ((uint32_t*)g_qs )[hrow * 64 + d] = pack_hl(w);
                        ((uint32_t*)g_qsw)[hrow * 64 + d] = pack_lh(w);
                    } else if (mat == 1) {
                        ((uint32_t*)g_ks)[hrow * 64 + d] = pack_hl(v);
                    } else {
                        g_v[hrow * DH_ + d] = v;
                    }
                }
            }
            __syncwarp();
        }
    }
}

// ---------------- WMMA attention — 32 q-rows/CTA, scores via attn_out ------
// smem: bB | bAn | bAw | red  = ~83KB -> 2 CTAs/SM
#define QB2  32
#define LD_K 136
#define LD_V 264
#define OFF_AN   34816
#define OFF_AW   (OFF_AN + QB2*LD_V*2)   // +16896 = 51712
#define OFF_RED  (OFF_AW + QB2*LD_V*2)   // 68608
#define SM2_BYTES (OFF_RED + 16384)      // 84992

__global__ __launch_bounds__(256)
void attn_wmma(float* __restrict__ attn_out)
{
    extern __shared__ char smraw[];
    __nv_bfloat16* bB  = (__nv_bfloat16*)smraw;
    __nv_bfloat16* bAn = (__nv_bfloat16*)(smraw + OFF_AN);
    __nv_bfloat16* bAw = (__nv_bfloat16*)(smraw + OFF_AW);
    float* red = (float*)(smraw + OFF_RED);

    const int q0 = blockIdx.x * QB2;
    const int hh = blockIdx.y, bb = blockIdx.z;
    const int tid = threadIdx.x, wid = tid >> 5, lane = tid & 31;
    const int bh = bb * H_ + hh;

    const __nv_bfloat16* Qn = g_qs  + ((size_t)bh * L_ + q0) * 128;
    const __nv_bfloat16* Qw = g_qsw + ((size_t)bh * L_ + q0) * 128;
    const __nv_bfloat16* Kh = g_ks  + (size_t)bh * L_ * 128;
    const __nv_bfloat16* Vt = g_vs  + (size_t)bh * DH_ * (2 * L_);
    float* gW = attn_out + ((size_t)bh * L_ + q0) * L_;   // 32 x 2048 block

    // load Q tiles (32 x 128 bf16 each) into bAn/bAw, ldm LD_K
    for (int u = tid; u < 1024; u += 256) {
        int half = u >> 9;
        int v = u & 511;
        int r = v >> 4, q = v & 15;
        uint4 src = ((const uint4*)((half ? Qw : Qn) + r * 128))[q];
        __nv_bfloat16* dst = half ? bAw : bAn;
        *(uint4*)(dst + r * LD_K + q * 8) = src;
    }

    // ---- phase 1: scores -> attn_out (raw) ----
    {
        wmma::fragment<wmma::accumulator, 16, 16, 16, float> sacc[2];
        for (int kc = 0; kc < L_; kc += 128) {
            __syncthreads();
            #pragma unroll
            for (int i = 0; i < 8; i++) {
                int u = tid + i * 256;           // 2048 uint4
                int r = u >> 4, q = u & 15;
                *(uint4*)(bB + r * LD_K + q * 8) =
                    ((const uint4*)(Kh + (size_t)(kc + r) * 128))[q];
            }
            __syncthreads();
            wmma::fill_fragment(sacc[0], 0.0f);
            wmma::fill_fragment(sacc[1], 0.0f);
            #pragma unroll
            for (int kt = 0; kt < 8; kt++) {
                wmma::fragment<wmma::matrix_b, 16, 16, 16, __nv_bfloat16,
                               wmma::col_major> b;
                wmma::load_matrix_sync(b, bB + (size_t)wid * 16 * LD_K + kt * 16, LD_K);
                #pragma unroll
                for (int mt = 0; mt < 2; mt++) {
                    wmma::fragment<wmma::matrix_a, 16, 16, 16, __nv_bfloat16,
                                   wmma::row_major> a;
                    wmma::load_matrix_sync(a, bAn + (mt * 16) * LD_K + kt * 16, LD_K);
                    wmma::mma_sync(sacc[mt], a, b, sacc[mt]);
                    wmma::load_matrix_sync(a, bAw + (mt * 16) * LD_K + kt * 16, LD_K);
                    wmma::mma_sync(sacc[mt], a, b, sacc[mt]);
                }
            }
            #pragma unroll
            for (int mt = 0; mt < 2; mt++)
                wmma::store_matrix_sync(gW + (size_t)(mt * 16) * L_ + kc + wid * 16,
                                        sacc[mt], L_, wmma::mem_row_major);
        }
    }
    __syncthreads();

    // ---- phase 2: softmax in gmem (L2-hot) ----
    for (int r = wid; r < QB2; r += 8) {
        float* row = gW + (size_t)r * L_;
        float m = -1e30f;
        for (int k = lane; k < L_; k += 32) m = fmaxf(m, row[k]);
        #pragma unroll
        for (int o = 16; o; o >>= 1) m = fmaxf(m, __shfl_xor_sync(0xffffffffu, m, o));
        float s = 0.f;
        for (int k = lane; k < L_; k += 32) {
            float e = __expf(row[k] - m);
            row[k] = e;
            s += e;
        }
        #pragma unroll
        for (int o = 16; o; o >>= 1) s += __shfl_xor_sync(0xffffffffu, s, o);
        float inv = 1.f / s;
        for (int k = lane; k < L_; k += 32)
            row[k] = row[k] * inv;
    }
    __syncthreads();

    // ---- phase 3: ctx = W @ V, pack straight into g_cs ----
    {
        wmma::fragment<wmma::accumulator, 16, 16, 16, float> cacc[2];
        wmma::fill_fragment(cacc[0], 0.0f);
        wmma::fill_fragment(cacc[1], 0.0f);
        const int nt = wid >> 1, kh = wid & 1;
        const int wr2 = tid >> 3, wks = (tid & 7) * 16;
        for (int c = 0; c < 16; c++) {               // 16 chunks x 128 keys
            __syncthreads();
            // Vt chunk [64][256 bf16] -> bB, ldm LD_V
            #pragma unroll
            for (int i = 0; i < 8; i++) {
                int u = tid + i * 256;               // 2048 uint4
                int r = u >> 5, q = u & 31;
                *(uint4*)(bB + r * LD_V + q * 8) =
                    ((const uint4*)(Vt + (size_t)r * (2 * L_) + c * 256))[q];
            }
            // W chunk (gmem weights) -> bAn (hi,lo), bAw (lo,hi): 32 x 128
            {
                const float* srow = gW + (size_t)wr2 * L_ + c * 128 + wks;
                uint32_t* wn = (uint32_t*)bAn + wr2 * (LD_V / 2) + wks;
                uint32_t* ww = (uint32_t*)bAw + wr2 * (LD_V / 2) + wks;
                #pragma unroll
                for (int j = 0; j < 16; j++) {
                    float w = srow[j];
                    wn[j] = pack_hl(w);
                    ww[j] = pack_lh(w);
                }
            }
            __syncthreads();
            #pragma unroll
            for (int kt = 0; kt < 8; kt++) {
                int k0 = kh * 128 + kt * 16;
                wmma::fragment<wmma::matrix_b, 16, 16, 16, __nv_bfloat16,
                               wmma::col_major> b;
                wmma::load_matrix_sync(b, bB + (size_t)nt * 16 * LD_V + k0, LD_V);
                #pragma unroll
                for (int mt = 0; mt < 2; mt++) {
                    wmma::fragment<wmma::matrix_a, 16, 16, 16, __nv_bfloat16,
                                   wmma::row_major> a;
                    wmma::load_matrix_sync(a, bAn + (mt * 16) * LD_V + k0, LD_V);
                    wmma::mma_sync(cacc[mt], a, b, cacc[mt]);
                    wmma::load_matrix_sync(a, bAw + (mt * 16) * LD_V + k0, LD_V);
                    wmma::mma_sync(cacc[mt], a, b, cacc[mt]);
                }
            }
        }
        __syncthreads();
        #pragma unroll
        for (int mt = 0; mt < 2; mt++)
            wmma::store_matrix_sync(red + wid * 512 + mt * 256, cacc[mt], 16,
                                    wmma::mem_row_major);
        __syncthreads();
        for (int e = tid; e < QB2 * 64; e += 256) {
            int m = e >> 6, col = e & 63;
            int nte = col >> 4;
            int off = (m >> 4) * 256 + (m & 15) * 16 + (col & 15);
            float v = red[(nte * 2 + 0) * 512 + off]
                    + red[(nte * 2 + 1) * 512 + off];
            size_t row = (size_t)bb * L_ + q0 + m;
            ((uint32_t*)g_cs)[row * 1024 + hh * 64 + col] = pack_hl(v);
        }
    }
}

// ---------------- launch ----------------
extern "C" void kernel_launch(void* const* d_in, const int* in_sizes, int n_in,
                              void* d_out, int out_size)
{
    const float* x  = (const float*)d_in[0];
    const float* Wq = (const float*)d_in[1];
    const float* bq = (const float*)d_in[2];
    const float* Wk = (const float*)d_in[3];
    const float* bk = (const float*)d_in[4];
    const float* Wv = (const float*)d_in[5];
    const float* bv = (const float*)d_in[6];
    const float* Wo = (const float*)d_in[7];
    const float* bo = (const float*)d_in[8];

    float* out  = (float*)d_out;                       // [B, L, D]
    float* attn = out + (size_t)M_ * D_;               // [B, H, L, L]

    cudaFuncSetAttribute(attn_wmma,
                         cudaFuncAttributeMaxDynamicSharedMemorySize, SM2_BYTES);

    // split projection inputs
    {
        int n4x = M_ * D_ / 4;
        int n4w = D_ * D_ / 4;
        split_x<<<(n4x + 255) / 256, 256>>>(x, n4x);
        split_w<<<(n4w + 255) / 256, 256>>>(Wq, 0, n4w);
        split_w<<<(n4w + 255) / 256, 256>>>(Wk, 1, n4w);
        split_w<<<(n4w + 255) / 256, 256>>>(Wv, 2, n4w);
        split_w<<<(n4w + 255) / 256, 256>>>(Wo, 3, n4w);
    }

    // QKV projections (epilogue writes split Q/K directly; V as float)
    dim3 gq(M_ / TM, D_ / TN, 3);
    mma_gemm<<<gq, 256>>>(0, bq, bk, bv, nullptr);

    // V transpose+split
    dim3 gv(L_ / 128, B_ * H_);
    v_split<<<gv, 256>>>();

    // attention (epilogue packs ctx straight into g_cs)
    dim3 ga(L_ / QB2, H_, B_);
    attn_wmma<<<ga, 256, SM2_BYTES>>>(attn);

    // output projection
    dim3 go(M_ / TM, D_ / TN, 1);
    mma_gemm<<<go, 256>>>(1, bo, bo, bo, out);
}

// round 14
// speedup vs baseline: 1.0237x; 1.0237x over previous
#include <cuda_runtime.h>
#include <cuda_bf16.h>
#include <mma.h>
#include <cstdint>

using namespace nvcuda;

#define B_   2
#define L_   2048
#define D_   1024
#define H_   16
#define DH_  64
#define M_   (B_*L_)          // 4096 rows
#define K2_  2048             // split-K (hi/lo interleaved)
#define SCALE 0.125f          // 1/sqrt(64)

// ---------------- scratch (static device memory; no allocs) ----------------
__device__ float g_v[M_*D_];
__device__ __nv_bfloat16 g_xs [M_*K2_];
__device__ __nv_bfloat16 g_cs [M_*K2_];
__device__ __nv_bfloat16 g_wqs[D_*K2_];   // weights, (hi,lo) interleaved
__device__ __nv_bfloat16 g_wks[D_*K2_];
__device__ __nv_bfloat16 g_wvs[D_*K2_];
__device__ __nv_bfloat16 g_wos[D_*K2_];
__device__ __nv_bfloat16 g_wqw[D_*K2_];   // weights, (lo,hi) swapped
__device__ __nv_bfloat16 g_wkw[D_*K2_];
__device__ __nv_bfloat16 g_wvw[D_*K2_];
__device__ __nv_bfloat16 g_wow[D_*K2_];
// attention split operands
__device__ __nv_bfloat16 g_qs [(size_t)B_*H_*L_*128];   // Q*scale (hi,lo)
__device__ __nv_bfloat16 g_qsw[(size_t)B_*H_*L_*128];   // Q*scale (lo,hi)
__device__ __nv_bfloat16 g_ks [(size_t)B_*H_*L_*128];   // K (hi,lo)
__device__ __nv_bfloat16 g_vs [(size_t)B_*H_*DH_*2*L_]; // V^T (hi,lo along key)

// ---------------- hi/lo bf16 pair packing ----------------
__device__ __forceinline__ uint32_t pack_hl(float x) {
    __nv_bfloat16 h = __float2bfloat16(x);
    __nv_bfloat16 l = __float2bfloat16(x - __bfloat162float(h));
    return (uint32_t)__bfloat16_as_ushort(h) |
           ((uint32_t)__bfloat16_as_ushort(l) << 16);
}
__device__ __forceinline__ uint32_t pack_lh(float x) {
    __nv_bfloat16 h = __float2bfloat16(x);
    __nv_bfloat16 l = __float2bfloat16(x - __bfloat162float(h));
    return (uint32_t)__bfloat16_as_ushort(l) |
           ((uint32_t)__bfloat16_as_ushort(h) << 16);
}

// ---------------- split kernels (inputs) ----------------
__global__ __launch_bounds__(256)
void split_x(const float* __restrict__ src, int n4)
{
    int i = blockIdx.x * 256 + threadIdx.x;
    if (i >= n4) return;
    float4 v = ((const float4*)src)[i];
    uint4 o;
    o.x = pack_hl(v.x); o.y = pack_hl(v.y); o.z = pack_hl(v.z); o.w = pack_hl(v.w);
    ((uint4*)g_xs)[i] = o;
}

__global__ __launch_bounds__(256)
void split_w(const float* __restrict__ src, int tag, int n4)
{
    __nv_bfloat16* dn = tag == 0 ? g_wqs : tag == 1 ? g_wks : tag == 2 ? g_wvs : g_wos;
    __nv_bfloat16* ds = tag == 0 ? g_wqw : tag == 1 ? g_wkw : tag == 2 ? g_wvw : g_wow;
    int i = blockIdx.x * 256 + threadIdx.x;
    if (i >= n4) return;
    float4 v = ((const float4*)src)[i];
    uint4 on, os;
    on.x = pack_hl(v.x); os.x = pack_lh(v.x);
    on.y = pack_hl(v.y); os.y = pack_lh(v.y);
    on.z = pack_hl(v.z); os.z = pack_lh(v.z);
    on.w = pack_hl(v.w); os.w = pack_lh(v.w);
    ((uint4*)dn)[i] = on;
    ((uint4*)ds)[i] = os;
}

// V transpose + split along key: g_v [bh][l][d] -> g_vs [bh][d][2l]
__global__ __launch_bounds__(256)
void v_split()
{
    __shared__ float tile[128 * 65];
    const int lb = blockIdx.x;
    const int bh = blockIdx.y;
    const int tid = threadIdx.x;
    const float* src = g_v + ((size_t)bh * L_ + lb * 128) * DH_;
    for (int i = 0; i < 8; i++) {
        int u = tid + i * 256;
        int r = u >> 4, q = u & 15;
        float4 t = ((const float4*)(src + (size_t)r * DH_))[q];
        tile[r * 65 + q * 4 + 0] = t.x;
        tile[r * 65 + q * 4 + 1] = t.y;
        tile[r * 65 + q * 4 + 2] = t.z;
        tile[r * 65 + q * 4 + 3] = t.w;
    }
    __syncthreads();
    const int d = tid >> 2, part = tid & 3;
    uint32_t* dst = (uint32_t*)g_vs + ((size_t)bh * DH_ + d) * L_
                    + lb * 128 + part * 32;
    #pragma unroll
    for (int j = 0; j < 32; j++) {
        float val = tile[(part * 32 + j) * 65 + d];
        dst[j] = pack_hl(val);
    }
}

// ---------------- WMMA GEMM (projections) — fused passes, fused split epi --
#define TM 128
#define TN 128
#define BK 32
#define NCH (K2_ / BK)        // 64
#define AS 40
#define STG 20

__global__ __launch_bounds__(256)
void mma_gemm(int which,
              const float* __restrict__ bi0, const float* __restrict__ bi1,
              const float* __restrict__ bi2, float* __restrict__ out_dst)
{
    __shared__ __align__(16) __nv_bfloat16 sA [TM * AS];
    __shared__ __align__(16) __nv_bfloat16 sBn[TN * AS];
    __shared__ __align__(16) __nv_bfloat16 sBw[TN * AS];
    __shared__ __align__(16) float stage[8][16 * STG];

    const int mat = blockIdx.z;
    const __nv_bfloat16* A = (which == 0) ? g_xs : g_cs;
    const __nv_bfloat16* Bn =
        (which == 1) ? g_wos : (mat == 0 ? g_wqs : (mat == 1 ? g_wks : g_wvs));
    const __nv_bfloat16* Bw =
        (which == 1) ? g_wow : (mat == 0 ? g_wqw : (mat == 1 ? g_wkw : g_wvw));
    const float* bias = (mat == 0) ? bi0 : (mat == 1 ? bi1 : bi2);

    const int row0 = blockIdx.x * TM;
    const int col0 = blockIdx.y * TN;
    const int tid  = threadIdx.x;
    const int wid  = tid >> 5, lane = tid & 31;
    const int wr   = wid >> 2;
    const int wc   = wid & 3;

    wmma::fragment<wmma::accumulator, 16, 16, 16, float> acc[4][2];
    #pragma unroll
    for (int i = 0; i < 4; i++)
        #pragma unroll
        for (int j = 0; j < 2; j++)
            wmma::fill_fragment(acc[i][j], 0.0f);

    const int r0c = tid >> 2,          q0c = tid & 3;
    const int r1c = (tid + 256) >> 2,  q1c = (tid + 256) & 3;

    for (int ch = 0; ch < NCH; ch++) {
        const int k0g = ch * BK;
        __syncthreads();
        *(uint4*)&sA [r0c * AS + q0c * 8] =
            *(const uint4*)(A  + (size_t)(row0 + r0c) * K2_ + k0g + q0c * 8);
        *(uint4*)&sA [r1c * AS + q1c * 8] =
            *(const uint4*)(A  + (size_t)(row0 + r1c) * K2_ + k0g + q1c * 8);
        *(uint4*)&sBn[r0c * AS + q0c * 8] =
            *(const uint4*)(Bn + (size_t)(col0 + r0c) * K2_ + k0g + q0c * 8);
        *(uint4*)&sBn[r1c * AS + q1c * 8] =
            *(const uint4*)(Bn + (size_t)(col0 + r1c) * K2_ + k0g + q1c * 8);
        *(uint4*)&sBw[r0c * AS + q0c * 8] =
            *(const uint4*)(Bw + (size_t)(col0 + r0c) * K2_ + k0g + q0c * 8);
        *(uint4*)&sBw[r1c * AS + q1c * 8] =
            *(const uint4*)(Bw + (size_t)(col0 + r1c) * K2_ + k0g + q1c * 8);
        __syncthreads();

        #pragma unroll
        for (int kk = 0; kk < 2; kk++) {
            const int k0 = kk * 16;
            wmma::fragment<wmma::matrix_a, 16, 16, 16, __nv_bfloat16,
                           wmma::row_major> af[4];
            #pragma unroll
            for (int i = 0; i < 4; i++)
                wmma::load_matrix_sync(af[i], &sA[(wr * 64 + i * 16) * AS + k0], AS);
            wmma::fragment<wmma::matrix_b, 16, 16, 16, __nv_bfloat16,
                           wmma::col_major> bfn[2], bfw[2];
            #pragma unroll
            for (int j = 0; j < 2; j++) {
                wmma::load_matrix_sync(bfn[j], &sBn[(wc * 32 + j * 16) * AS + k0], AS);
                wmma::load_matrix_sync(bfw[j], &sBw[(wc * 32 + j * 16) * AS + k0], AS);
            }
            #pragma unroll
            for (int i = 0; i < 4; i++)
                #pragma unroll
                for (int j = 0; j < 2; j++) {
                    wmma::mma_sync(acc[i][j], af[i], bfn[j], acc[i][j]);
                    wmma::mma_sync(acc[i][j], af[i], bfw[j], acc[i][j]);
                }
        }
    }

    // ---- epilogue: bias add + destination-specific packing ----
    __syncthreads();
    #pragma unroll
    for (int i = 0; i < 4; i++) {
        #pragma unroll
        for (int j = 0; j < 2; j++) {
            wmma::store_matrix_sync(&stage[wid][0], acc[i][j], STG,
                                    wmma::mem_row_major);
            __syncwarp();
            #pragma unroll
            for (int e = 0; e < 8; e++) {
                int idx = lane * 8 + e;
                int rr = idx >> 4, cc = idx & 15;
                int m = row0 + wr * 64 + i * 16 + rr;
                int n = col0 + wc * 32 + j * 16 + cc;
                float v = stage[wid][rr * STG + cc] + bias[n];
                if (which == 1) {
                    out_dst[(size_t)m * D_ + n] = v;
                } else {
                    int l = m & (L_ - 1), bb = m >> 11;
                    int h = n >> 6, d = n & 63;
                    size_t hrow = ((size_t)(bb * H_ + h) * L_ + l);
                    if (mat == 0) {
                        float w = v * SCALE;
                        ((uint32_t*)g_qs )[hrow * 64 + d] = pack_hl(w);
                        ((uint32_t*)g_qsw)[hrow * 64 + d] = pack_lh(w);
                    } else if (mat == 1) {
                        ((uint32_t*)g_ks)[hrow * 64 + d] = pack_hl(v);
                    } else {
                        g_v[hrow * DH_ + d] = v;
                    }
                }
            }
            __syncwarp();
        }
    }
}

// ---------------- WMMA attention — 16 q-rows/CTA (3 CTAs/SM), fused epi ----
// smem: bB | bAn | bAw | red  = ~60KB -> 3 CTAs/SM
#define QB2  16
#define LD_K 136
#define LD_V 264
#define OFF_AN   34816
#define OFF_AW   (OFF_AN + QB2*LD_V*2)   // 43264
#define OFF_RED  (OFF_AW + QB2*LD_V*2)   // 51712
#define SM2_BYTES (OFF_RED + 8192)       // 59904

__global__ __launch_bounds__(256)
void attn_wmma(float* __restrict__ attn_out)
{
    extern __shared__ char smraw[];
    __nv_bfloat16* bB  = (__nv_bfloat16*)smraw;
    __nv_bfloat16* bAn = (__nv_bfloat16*)(smraw + OFF_AN);
    __nv_bfloat16* bAw = (__nv_bfloat16*)(smraw + OFF_AW);
    float* red = (float*)(smraw + OFF_RED);

    const int q0 = blockIdx.x * QB2;
    const int hh = blockIdx.y, bb = blockIdx.z;
    const int tid = threadIdx.x, wid = tid >> 5, lane = tid & 31;
    const int bh = bb * H_ + hh;

    const __nv_bfloat16* Qn = g_qs  + ((size_t)bh * L_ + q0) * 128;
    const __nv_bfloat16* Qw = g_qsw + ((size_t)bh * L_ + q0) * 128;
    const __nv_bfloat16* Kh = g_ks  + (size_t)bh * L_ * 128;
    const __nv_bfloat16* Vt = g_vs  + (size_t)bh * DH_ * (2 * L_);
    float* gW = attn_out + ((size_t)bh * L_ + q0) * L_;   // 16 x 2048 block

    // load Q tiles (16 x 128 bf16 each) into bAn/bAw, ldm LD_K
    for (int u = tid; u < 512; u += 256) {
        int half = u >> 8;
        int v = u & 255;
        int r = v >> 4, q = v & 15;
        uint4 src = ((const uint4*)((half ? Qw : Qn) + r * 128))[q];
        __nv_bfloat16* dst = half ? bAw : bAn;
        *(uint4*)(dst + r * LD_K + q * 8) = src;
    }

    // ---- phase 1: scores -> attn_out (raw) ----
    {
        wmma::fragment<wmma::accumulator, 16, 16, 16, float> sacc;
        for (int kc = 0; kc < L_; kc += 128) {
            __syncthreads();
            #pragma unroll
            for (int i = 0; i < 8; i++) {
                int u = tid + i * 256;           // 2048 uint4
                int r = u >> 4, q = u & 15;
                *(uint4*)(bB + r * LD_K + q * 8) =
                    ((const uint4*)(Kh + (size_t)(kc + r) * 128))[q];
            }
            __syncthreads();
            wmma::fill_fragment(sacc, 0.0f);
            #pragma unroll
            for (int kt = 0; kt < 8; kt++) {
                wmma::fragment<wmma::matrix_a, 16, 16, 16, __nv_bfloat16,
                               wmma::row_major> a;
                wmma::fragment<wmma::matrix_b, 16, 16, 16, __nv_bfloat16,
                               wmma::col_major> b;
                wmma::load_matrix_sync(b, bB + (size_t)wid * 16 * LD_K + kt * 16, LD_K);
                wmma::load_matrix_sync(a, bAn + kt * 16, LD_K);
                wmma::mma_sync(sacc, a, b, sacc);
                wmma::load_matrix_sync(a, bAw + kt * 16, LD_K);
                wmma::mma_sync(sacc, a, b, sacc);
            }
            wmma::store_matrix_sync(gW + kc + wid * 16, sacc, L_,
                                    wmma::mem_row_major);
        }
    }
    __syncthreads();

    // ---- phase 2: softmax in gmem (L2-hot) ----
    for (int r = wid; r < QB2; r += 8) {
        float* row = gW + (size_t)r * L_;
        float m = -1e30f;
        for (int k = lane; k < L_; k += 32) m = fmaxf(m, row[k]);
        #pragma unroll
        for (int o = 16; o; o >>= 1) m = fmaxf(m, __shfl_xor_sync(0xffffffffu, m, o));
        float s = 0.f;
        for (int k = lane; k < L_; k += 32) {
            float e = __expf(row[k] - m);
            row[k] = e;
            s += e;
        }
        #pragma unroll
        for (int o = 16; o; o >>= 1) s += __shfl_xor_sync(0xffffffffu, s, o);
        float inv = 1.f / s;
        for (int k = lane; k < L_; k += 32)
            row[k] = row[k] * inv;
    }
    __syncthreads();

    // ---- phase 3: ctx = W @ V, pack straight into g_cs ----
    {
        wmma::fragment<wmma::accumulator, 16, 16, 16, float> cacc;
        wmma::fill_fragment(cacc, 0.0f);
        const int nt = wid >> 1, kh = wid & 1;
        const int wr2 = tid >> 4, wks = (tid & 15) * 8;
        for (int c = 0; c < 16; c++) {               // 16 chunks x 128 keys
            __syncthreads();
            // Vt chunk [64][256 bf16] -> bB, ldm LD_V
            #pragma unroll
            for (int i = 0; i < 8; i++) {
                int u = tid + i * 256;               // 2048 uint4
                int r = u >> 5, q = u & 31;
                *(uint4*)(bB + r * LD_V + q * 8) =
                    ((const uint4*)(Vt + (size_t)r * (2 * L_) + c * 256))[q];
            }
            // W chunk (gmem weights) -> bAn (hi,lo), bAw (lo,hi): 16 x 128
            {
                const float* srow = gW + (size_t)wr2 * L_ + c * 128 + wks;
                uint32_t* wn = (uint32_t*)bAn + wr2 * (LD_V / 2) + wks;
                uint32_t* ww = (uint32_t*)bAw + wr2 * (LD_V / 2) + wks;
                #pragma unroll
                for (int j = 0; j < 8; j++) {
                    float w = srow[j];
                    wn[j] = pack_hl(w);
                    ww[j] = pack_lh(w);
                }
            }
            __syncthreads();
            #pragma unroll
            for (int kt = 0; kt < 8; kt++) {
                int k0 = kh * 128 + kt * 16;
                wmma::fragment<wmma::matrix_a, 16, 16, 16, __nv_bfloat16,
                               wmma::row_major> a;
                wmma::fragment<wmma::matrix_b, 16, 16, 16, __nv_bfloat16,
                               wmma::col_major> b;
                wmma::load_matrix_sync(b, bB + (size_t)nt * 16 * LD_V + k0, LD_V);
                wmma::load_matrix_sync(a, bAn + k0, LD_V);
                wmma::mma_sync(cacc, a, b, cacc);
                wmma::load_matrix_sync(a, bAw + k0, LD_V);
                wmma::mma_sync(cacc, a, b, cacc);
            }
        }
        __syncthreads();
        wmma::store_matrix_sync(red + wid * 256, cacc, 16, wmma::mem_row_major);
        __syncthreads();
        for (int e = tid; e < QB2 * 64; e += 256) {
            int m = e >> 6, col = e & 63;
            int w0 = (col >> 4) << 1;
            float v = red[w0 * 256 + m * 16 + (col & 15)]
                    + red[(w0 + 1) * 256 + m * 16 + (col & 15)];
            size_t row = (size_t)bb * L_ + q0 + m;
            ((uint32_t*)g_cs)[row * 1024 + hh * 64 + col] = pack_hl(v);
        }
    }
}

// ---------------- launch ----------------
extern "C" void kernel_launch(void* const* d_in, const int* in_sizes, int n_in,
                              void* d_out, int out_size)
{
    const float* x  = (const float*)d_in[0];
    const float* Wq = (const float*)d_in[1];
    const float* bq = (const float*)d_in[2];
    const float* Wk = (const float*)d_in[3];
    const float* bk = (const float*)d_in[4];
    const float* Wv = (const float*)d_in[5];
    const float* bv = (const float*)d_in[6];
    const float* Wo = (const float*)d_in[7];
    const float* bo = (const float*)d_in[8];

    float* out  = (float*)d_out;                       // [B, L, D]
    float* attn = out + (size_t)M_ * D_;               // [B, H, L, L]

    cudaFuncSetAttribute(attn_wmma,
                         cudaFuncAttributeMaxDynamicSharedMemorySize, SM2_BYTES);

    // split projection inputs
    {
        int n4x = M_ * D_ / 4;
        int n4w = D_ * D_ / 4;
        split_x<<<(n4x + 255) / 256, 256>>>(x, n4x);
        split_w<<<(n4w + 255) / 256, 256>>>(Wq, 0, n4w);
        split_w<<<(n4w + 255) / 256, 256>>>(Wk, 1, n4w);
        split_w<<<(n4w + 255) / 256, 256>>>(Wv, 2, n4w);
        split_w<<<(n4w + 255) / 256, 256>>>(Wo, 3, n4w);
    }

    // QKV projections (epilogue writes split Q/K directly; V as float)
    dim3 gq(M_ / TM, D_ / TN, 3);
    mma_gemm<<<gq, 256>>>(0, bq, bk, bv, nullptr);

    // V transpose+split
    dim3 gv(L_ / 128, B_ * H_);
    v_split<<<gv, 256>>>();

    // attention (epilogue packs ctx straight into g_cs)
    dim3 ga(L_ / QB2, H_, B_);
    attn_wmma<<<ga, 256, SM2_BYTES>>>(attn);

    // output projection
    dim3 go(M_ / TM, D_ / TN, 1);
    mma_gemm<<<go, 256>>>(1, bo, bo, bo, out);
}